// round 14
// baseline (speedup 1.0000x reference)
#include <cuda_runtime.h>
#include <cuda_bf16.h>
#include <cstdint>

#define TOKENS 4096
#define DIMSZ  1024
#define NSEQ   2048
#define HEADS  16
#define QKV_N  3072

typedef __nv_bfloat16 bf16;

// Scratch (device globals per harness rules; 16B-aligned for cp.async/uint4)
__device__ __align__(16) bf16 g_xnh [TOKENS * DIMSZ];
__device__ __align__(16) bf16 g_xnl [TOKENS * DIMSZ];
__device__ __align__(16) bf16 g_wqh [QKV_N * DIMSZ];
__device__ __align__(16) bf16 g_wql [QKV_N * DIMSZ];
__device__ __align__(16) bf16 g_qkvh[TOKENS * QKV_N];   // split QKV (Q pre-scaled)
__device__ __align__(16) bf16 g_qkvl[TOKENS * QKV_N];
__device__ __align__(16) bf16 g_ath [TOKENS * DIMSZ];
__device__ __align__(16) bf16 g_atl [TOKENS * DIMSZ];
__device__ __align__(16) bf16 g_woh [DIMSZ * DIMSZ];
__device__ __align__(16) bf16 g_wol [DIMSZ * DIMSZ];

__device__ __forceinline__ uint32_t smem_u32(const void* p) {
    uint32_t a;
    asm("{ .reg .u64 t; cvta.to.shared.u64 t, %1; cvt.u32.u64 %0, t; }" : "=r"(a) : "l"(p));
    return a;
}
__device__ __forceinline__ void split(float v, bf16& h, bf16& l) {
    h = __float2bfloat16(v);
    l = __float2bfloat16(v - __bfloat162float(h));
}
__device__ __forceinline__ void ldsm_x4(uint32_t* r, uint32_t addr) {
    asm volatile("ldmatrix.sync.aligned.m8n8.x4.shared.b16 {%0,%1,%2,%3}, [%4];"
        : "=r"(r[0]), "=r"(r[1]), "=r"(r[2]), "=r"(r[3]) : "r"(addr));
}
__device__ __forceinline__ void ldsm_x4_t(uint32_t* r, uint32_t addr) {
    asm volatile("ldmatrix.sync.aligned.m8n8.x4.trans.shared.b16 {%0,%1,%2,%3}, [%4];"
        : "=r"(r[0]), "=r"(r[1]), "=r"(r[2]), "=r"(r[3]) : "r"(addr));
}
__device__ __forceinline__ void mma_bf16(float* c, const uint32_t* a, uint32_t b0, uint32_t b1) {
    asm volatile(
        "mma.sync.aligned.m16n8k16.row.col.f32.bf16.bf16.f32 "
        "{%0,%1,%2,%3}, {%4,%5,%6,%7}, {%8,%9}, {%0,%1,%2,%3};"
        : "+f"(c[0]), "+f"(c[1]), "+f"(c[2]), "+f"(c[3])
        : "r"(a[0]), "r"(a[1]), "r"(a[2]), "r"(a[3]), "r"(b0), "r"(b1));
}
__device__ __forceinline__ void psplit2(float x, float y, uint32_t& ph, uint32_t& pl) {
    bf16 hx = __float2bfloat16(x), hy = __float2bfloat16(y);
    bf16 lx = __float2bfloat16(x - __bfloat162float(hx));
    bf16 ly = __float2bfloat16(y - __bfloat162float(hy));
    ph = ((uint32_t)__bfloat16_as_ushort(hy) << 16) | __bfloat16_as_ushort(hx);
    pl = ((uint32_t)__bfloat16_as_ushort(ly) << 16) | __bfloat16_as_ushort(lx);
}

#define CP16(dst, src)  asm volatile("cp.async.cg.shared.global [%0], [%1], 16;" :: "r"(dst), "l"(src))
#define CP_COMMIT()     asm volatile("cp.async.commit_group;" ::: "memory")
#define CP_WAIT(n)      asm volatile("cp.async.wait_group %0;" :: "n"(n) : "memory")

// ---------------------------------------------------------------------------
// RMSNorm -> split bf16 hi/lo
// ---------------------------------------------------------------------------
__global__ void __launch_bounds__(256) rmsnorm_kernel(const float* __restrict__ x,
                                                      const float* __restrict__ gamma) {
    int row = blockIdx.x;
    int tid = threadIdx.x;
    const float4 v = ((const float4*)(x + (size_t)row * DIMSZ))[tid];
    float ss = v.x * v.x + v.y * v.y + v.z * v.z + v.w * v.w;
#pragma unroll
    for (int off = 16; off >= 1; off >>= 1)
        ss += __shfl_xor_sync(0xffffffffu, ss, off);
    __shared__ float red[8];
    int lane = tid & 31, wid = tid >> 5;
    if (lane == 0) red[wid] = ss;
    __syncthreads();
    if (wid == 0) {
        float t = (lane < 8) ? red[lane] : 0.0f;
#pragma unroll
        for (int off = 4; off >= 1; off >>= 1)
            t += __shfl_xor_sync(0xffffffffu, t, off);
        if (lane == 0) red[0] = t;
    }
    __syncthreads();
    float norm = fmaxf(sqrtf(red[0]), 1e-12f);
    float scl = 32.0f / norm;
    const float4 g = ((const float4*)gamma)[tid];
    float o0 = v.x * scl * g.x, o1 = v.y * scl * g.y;
    float o2 = v.z * scl * g.z, o3 = v.w * scl * g.w;
    __align__(8) bf16 hh[4], ll[4];
    split(o0, hh[0], ll[0]); split(o1, hh[1], ll[1]);
    split(o2, hh[2], ll[2]); split(o3, hh[3], ll[3]);
    size_t off = (size_t)row * DIMSZ + tid * 4;
    *(uint2*)&g_xnh[off] = *(uint2*)hh;
    *(uint2*)&g_xnl[off] = *(uint2*)ll;
}

// ---------------------------------------------------------------------------
// Transpose + split: W[K][N] fp32 -> Th/Tl[N][K] bf16
// ---------------------------------------------------------------------------
__global__ void tsplit_kernel(const float* __restrict__ W, bf16* __restrict__ Th,
                              bf16* __restrict__ Tl, int K, int N) {
    __shared__ float s[32][33];
    int tx = threadIdx.x, ty = threadIdx.y;
    int n0 = blockIdx.x * 32, k0 = blockIdx.y * 32;
#pragma unroll
    for (int j = 0; j < 32; j += 8)
        s[ty + j][tx] = W[(size_t)(k0 + ty + j) * N + n0 + tx];
    __syncthreads();
#pragma unroll
    for (int j = 0; j < 32; j += 8) {
        float v = s[tx][ty + j];
        bf16 h, l; split(v, h, l);
        size_t o = (size_t)(n0 + ty + j) * K + k0 + tx;
        Th[o] = h; Tl[o] = l;
    }
}

// ---------------------------------------------------------------------------
// Split-bf16 mma.sync GEMM, cp.async 2-stage pipeline, K-slab 64.
// C[M,N] = A[M,1024] @ Bt[N,1024]^T ~= Ah·Bh + Ah·Bl + Al·Bh
// SPLIT=1: write split bf16 (Ch/Cl), scaling cols < 1024 by 0.125 (Q).
// Stage = 4 arrays of 128 rows x 64 bf16, pitch 72 (144B: 16B-aligned rows,
// conflict-free ldmatrix). 2 stages = 147456 B -> 1 CTA/SM, 32 barriers/CTA.
// ---------------------------------------------------------------------------
#define GP    72
#define G_AB  (128 * GP * 2)       // 18432 B per array
#define G_STG (4 * G_AB)           // 73728 B per stage
#define GEMM_SMEM (2 * G_STG)      // 147456 B

template<int SPLIT>
__global__ void __launch_bounds__(256) gemm_mma(
        const bf16* __restrict__ Ah, const bf16* __restrict__ Al,
        const bf16* __restrict__ Bh, const bf16* __restrict__ Bl,
        float* __restrict__ C, bf16* __restrict__ Ch, bf16* __restrict__ Cl, int N) {
    extern __shared__ char smraw[];
    uint32_t sbase = smem_u32(smraw);
    int tid = threadIdx.x, lane = tid & 31, wid = tid >> 5;
    int wm = wid >> 2, wn = wid & 3;
    int bm = blockIdx.y * 128, bn = blockIdx.x * 128;

    const bf16* g0 = Ah + (size_t)bm * DIMSZ;
    const bf16* g1 = Al + (size_t)bm * DIMSZ;
    const bf16* g2 = Bh + (size_t)bn * DIMSZ;
    const bf16* g3 = Bl + (size_t)bn * DIMSZ;

    int rowA = wm * 64 + (lane & 7) + ((lane >> 3) & 1) * 8;
    int koffA = (lane >> 4) * 8;
    uint32_t aoff = (uint32_t)(rowA * GP + koffA) * 2;
    int nrow = wn * 32 + (lane & 7) + ((lane >> 4) & 1) * 8;
    int koffB = ((lane >> 3) & 1) * 8;
    uint32_t boff = (uint32_t)(nrow * GP + koffB) * 2;

    float c[4][4][4];
#pragma unroll
    for (int i = 0; i < 4; i++)
#pragma unroll
        for (int j = 0; j < 4; j++)
#pragma unroll
            for (int k = 0; k < 4; k++) c[i][j][k] = 0.0f;

    // copy coords: 1024 16B-chunks per array per slab; 4 per thread per array
#define G_ISSUE(s, stg) do {                                                      \
    int k0_ = (s) * 64;                                                           \
    uint32_t db_ = sbase + (stg) * G_STG;                                         \
    _Pragma("unroll")                                                             \
    for (int t = 0; t < 4; t++) {                                                 \
        int idx = tid + t * 256;                                                  \
        int row = idx >> 3, ch = (idx & 7) * 8;                                   \
        uint32_t doff = (uint32_t)(row * GP + ch) * 2;                            \
        CP16(db_ + 0 * G_AB + doff, g0 + (size_t)row * DIMSZ + k0_ + ch);         \
        CP16(db_ + 1 * G_AB + doff, g1 + (size_t)row * DIMSZ + k0_ + ch);         \
        CP16(db_ + 2 * G_AB + doff, g2 + (size_t)row * DIMSZ + k0_ + ch);         \
        CP16(db_ + 3 * G_AB + doff, g3 + (size_t)row * DIMSZ + k0_ + ch);         \
    }                                                                             \
    CP_COMMIT();                                                                  \
} while (0)

    G_ISSUE(0, 0);

    const int NSLAB = DIMSZ / 64;  // 16
    for (int s = 0; s < NSLAB; s++) {
        int stg = s & 1;
        if (s < NSLAB - 1) { G_ISSUE(s + 1, stg ^ 1); CP_WAIT(1); }
        else               { CP_WAIT(0); }
        __syncthreads();
        uint32_t sb = sbase + stg * G_STG;
        uint32_t aHb = sb + aoff, aLb = sb + G_AB + aoff;
        uint32_t bHb = sb + 2 * G_AB + boff, bLb = sb + 3 * G_AB + boff;
#pragma unroll
        for (int kk = 0; kk < 4; kk++) {
            uint32_t ko = kk * 32;
            uint32_t aH[4][4], aL[4][4], bH[2][4], bL[2][4];
#pragma unroll
            for (int mt = 0; mt < 4; mt++) {
                ldsm_x4(aH[mt], aHb + mt * (16 * GP * 2) + ko);
                ldsm_x4(aL[mt], aLb + mt * (16 * GP * 2) + ko);
            }
#pragma unroll
            for (int pr = 0; pr < 2; pr++) {
                ldsm_x4(bH[pr], bHb + pr * (16 * GP * 2) + ko);
                ldsm_x4(bL[pr], bLb + pr * (16 * GP * 2) + ko);
            }
#pragma unroll
            for (int mt = 0; mt < 4; mt++)
#pragma unroll
                for (int nt = 0; nt < 4; nt++) {
                    int pr = nt >> 1, hf = (nt & 1) * 2;
                    mma_bf16(c[mt][nt], aH[mt], bH[pr][hf], bH[pr][hf + 1]);
                    mma_bf16(c[mt][nt], aH[mt], bL[pr][hf], bL[pr][hf + 1]);
                    mma_bf16(c[mt][nt], aL[mt], bH[pr][hf], bH[pr][hf + 1]);
                }
        }
        __syncthreads();
    }

    float sc = (SPLIT && bn < 1024) ? 0.125f : 1.0f;
#pragma unroll
    for (int mt = 0; mt < 4; mt++)
#pragma unroll
        for (int nt = 0; nt < 4; nt++) {
            int r0 = bm + wm * 64 + mt * 16 + (lane >> 2);
            int col = bn + wn * 32 + nt * 8 + (lane & 3) * 2;
            if (SPLIT) {
#pragma unroll
                for (int hrow = 0; hrow < 2; hrow++) {
                    float v0 = c[mt][nt][2 * hrow] * sc, v1 = c[mt][nt][2 * hrow + 1] * sc;
                    uint32_t ph, pl;
                    psplit2(v0, v1, ph, pl);
                    size_t o = (size_t)(r0 + 8 * hrow) * N + col;
                    *(uint32_t*)&Ch[o] = ph;
                    *(uint32_t*)&Cl[o] = pl;
                }
            } else {
                *(float2*)&C[(size_t)r0 * N + col]       = make_float2(c[mt][nt][0], c[mt][nt][1]);
                *(float2*)&C[(size_t)(r0 + 8) * N + col] = make_float2(c[mt][nt][2], c[mt][nt][3]);
            }
        }
#undef G_ISSUE
}

// ---------------------------------------------------------------------------
// Causal flash attention, split-bf16 mma.sync, cp.async double-buffered K/V.
// K/V already split in g_qkvh/g_qkvl (Q pre-scaled by 0.125 in GEMM epilogue).
// ---------------------------------------------------------------------------
#define AP    72
#define A_AB  (64 * AP * 2)        // 9216 B per array
#define A_STG (4 * A_AB)           // 36864 B per stage
#define ATTN_SMEM (2 * A_STG)      // 73728 B

__global__ void __launch_bounds__(128) attn_mma() {
    extern __shared__ char smraw[];
    uint32_t sbase = smem_u32(smraw);
    int tid = threadIdx.x, lane = tid & 31, w = tid >> 5;
    int qb = blockIdx.x, bh = blockIdx.y;
    int b = bh >> 4, h = bh & 15;
    int t0 = b * NSEQ;

#define A_ISSUE(kb, stg) do {                                                        \
    uint32_t db_ = sbase + (stg) * A_STG;                                            \
    _Pragma("unroll")                                                                \
    for (int t = 0; t < 4; t++) {                                                    \
        int idx = tid + t * 128;                                                     \
        int row = idx >> 3, ch = (idx & 7) * 8;                                      \
        uint32_t doff = (uint32_t)(row * AP + ch) * 2;                               \
        size_t g = (size_t)(t0 + (kb) * 64 + row) * QKV_N + h * 64 + ch;             \
        CP16(db_ + 0 * A_AB + doff, &g_qkvh[g + 1024]);                              \
        CP16(db_ + 1 * A_AB + doff, &g_qkvl[g + 1024]);                              \
        CP16(db_ + 2 * A_AB + doff, &g_qkvh[g + 2048]);                              \
        CP16(db_ + 3 * A_AB + doff, &g_qkvl[g + 2048]);                              \
    }                                                                                \
    CP_COMMIT();                                                                     \
} while (0)

    A_ISSUE(0, 0);   // K/V block 0 -> stage 0 (async, overlaps Q staging)

    // stage Q (bf16, pre-scaled) into stage-1 Kh/Kl regions
#pragma unroll
    for (int t = 0; t < 4; t++) {
        int idx = tid + t * 128;
        int row = idx >> 3, ch = (idx & 7) * 8;
        size_t g = (size_t)(t0 + qb * 64 + row) * QKV_N + h * 64 + ch;
        uint32_t doff = (uint32_t)(row * AP + ch) * 2;
        *(uint4*)(smraw + A_STG + 0 * A_AB + doff) = *(const uint4*)&g_qkvh[g];
        *(uint4*)(smraw + A_STG + 1 * A_AB + doff) = *(const uint4*)&g_qkvl[g];
    }
    __syncthreads();
    uint32_t qh[4][4], ql[4][4];
    {
        int rowA = w * 16 + (lane & 7) + ((lane >> 3) & 1) * 8;
        int koffA = (lane >> 4) * 8;
        uint32_t aHb = sbase + A_STG + 0 * A_AB + (uint32_t)(rowA * AP + koffA) * 2;
        uint32_t aLb = sbase + A_STG + 1 * A_AB + (uint32_t)(rowA * AP + koffA) * 2;
#pragma unroll
        for (int k = 0; k < 4; k++) {
            ldsm_x4(qh[k], aHb + k * 32);
            ldsm_x4(ql[k], aLb + k * 32);
        }
    }
    __syncthreads();   // all warps have Q frags before stage-1 gets overwritten

    float o[8][4];
#pragma unroll
    for (int j = 0; j < 8; j++)
#pragma unroll
        for (int v = 0; v < 4; v++) o[j][v] = 0.0f;
    float m0 = -1e30f, m1 = -1e30f, l0 = 0.0f, l1 = 0.0f;

    int nrowB = (lane & 7) + ((lane >> 4) & 1) * 8;
    int koffB = ((lane >> 3) & 1) * 8;
    uint32_t kboff = (uint32_t)(nrowB * AP + koffB) * 2;
    uint32_t vboff = (uint32_t)((lane & 15) * AP + ((lane >> 4) & 1) * 8) * 2;

    for (int kb = 0; kb <= qb; kb++) {
        int stg = kb & 1;
        if (kb < qb) { A_ISSUE(kb + 1, stg ^ 1); CP_WAIT(1); }
        else         { CP_WAIT(0); }
        __syncthreads();
        uint32_t sb = sbase + stg * A_STG;
        uint32_t kHb = sb + kboff, kLb = sb + A_AB + kboff;
        uint32_t vHb = sb + 2 * A_AB + vboff, vLb = sb + 3 * A_AB + vboff;

        // ---- S = Q K^T ----
        float s[8][4];
#pragma unroll
        for (int j = 0; j < 8; j++)
#pragma unroll
            for (int v = 0; v < 4; v++) s[j][v] = 0.0f;
#pragma unroll
        for (int k = 0; k < 4; k++)
#pragma unroll
            for (int pr = 0; pr < 4; pr++) {
                uint32_t bh_[4], bl_[4];
                ldsm_x4(bh_, kHb + pr * (16 * AP * 2) + k * 32);
                ldsm_x4(bl_, kLb + pr * (16 * AP * 2) + k * 32);
                mma_bf16(s[2 * pr],     qh[k], bh_[0], bh_[1]);
                mma_bf16(s[2 * pr],     qh[k], bl_[0], bl_[1]);
                mma_bf16(s[2 * pr],     ql[k], bh_[0], bh_[1]);
                mma_bf16(s[2 * pr + 1], qh[k], bh_[2], bh_[3]);
                mma_bf16(s[2 * pr + 1], qh[k], bl_[2], bl_[3]);
                mma_bf16(s[2 * pr + 1], ql[k], bh_[2], bh_[3]);
            }

        int r0 = w * 16 + (lane >> 2);
        int cb = (lane & 3) * 2;
        if (kb == qb) {
#pragma unroll
            for (int j = 0; j < 8; j++) {
                int c0 = 8 * j + cb;
                if (c0     > r0    ) s[j][0] = -1e30f;
                if (c0 + 1 > r0    ) s[j][1] = -1e30f;
                if (c0     > r0 + 8) s[j][2] = -1e30f;
                if (c0 + 1 > r0 + 8) s[j][3] = -1e30f;
            }
        }

        // ---- online softmax (2 rows/thread) ----
        float tm0 = -1e30f, tm1 = -1e30f;
#pragma unroll
        for (int j = 0; j < 8; j++) {
            tm0 = fmaxf(tm0, fmaxf(s[j][0], s[j][1]));
            tm1 = fmaxf(tm1, fmaxf(s[j][2], s[j][3]));
        }
        tm0 = fmaxf(tm0, __shfl_xor_sync(0xffffffffu, tm0, 1));
        tm0 = fmaxf(tm0, __shfl_xor_sync(0xffffffffu, tm0, 2));
        tm1 = fmaxf(tm1, __shfl_xor_sync(0xffffffffu, tm1, 1));
        tm1 = fmaxf(tm1, __shfl_xor_sync(0xffffffffu, tm1, 2));
        float mn0 = fmaxf(m0, tm0), mn1 = fmaxf(m1, tm1);
        float al0 = __expf(m0 - mn0), al1 = __expf(m1 - mn1);
        m0 = mn0; m1 = mn1;
        float sum0 = 0.0f, sum1 = 0.0f;
#pragma unroll
        for (int j = 0; j < 8; j++) {
            s[j][0] = __expf(s[j][0] - mn0); sum0 += s[j][0];
            s[j][1] = __expf(s[j][1] - mn0); sum0 += s[j][1];
            s[j][2] = __expf(s[j][2] - mn1); sum1 += s[j][2];
            s[j][3] = __expf(s[j][3] - mn1); sum1 += s[j][3];
        }
        sum0 += __shfl_xor_sync(0xffffffffu, sum0, 1);
        sum0 += __shfl_xor_sync(0xffffffffu, sum0, 2);
        sum1 += __shfl_xor_sync(0xffffffffu, sum1, 1);
        sum1 += __shfl_xor_sync(0xffffffffu, sum1, 2);
        l0 = l0 * al0 + sum0;
        l1 = l1 * al1 + sum1;
#pragma unroll
        for (int j = 0; j < 8; j++) {
            o[j][0] *= al0; o[j][1] *= al0;
            o[j][2] *= al1; o[j][3] *= al1;
        }

        // ---- O += P V ----
#pragma unroll
        for (int kk = 0; kk < 4; kk++) {
            uint32_t ph[4], pl[4];
            psplit2(s[2 * kk][0],     s[2 * kk][1],     ph[0], pl[0]);
            psplit2(s[2 * kk][2],     s[2 * kk][3],     ph[1], pl[1]);
            psplit2(s[2 * kk + 1][0], s[2 * kk + 1][1], ph[2], pl[2]);
            psplit2(s[2 * kk + 1][2], s[2 * kk + 1][3], ph[3], pl[3]);
#pragma unroll
            for (int pr = 0; pr < 4; pr++) {
                uint32_t bvh[4], bvl[4];
                ldsm_x4_t(bvh, vHb + (uint32_t)(kk * 16 * AP + pr * 16) * 2);
                ldsm_x4_t(bvl, vLb + (uint32_t)(kk * 16 * AP + pr * 16) * 2);
                mma_bf16(o[2 * pr],     ph, bvh[0], bvh[1]);
                mma_bf16(o[2 * pr],     pl, bvh[0], bvh[1]);
                mma_bf16(o[2 * pr],     ph, bvl[0], bvl[1]);
                mma_bf16(o[2 * pr + 1], ph, bvh[2], bvh[3]);
                mma_bf16(o[2 * pr + 1], pl, bvh[2], bvh[3]);
                mma_bf16(o[2 * pr + 1], ph, bvl[2], bvl[3]);
            }
        }
        __syncthreads();   // all warps done with this stage before it is refilled
    }

    // ---- epilogue ----
    float inv0 = 1.0f / l0, inv1 = 1.0f / l1;
    int r0 = w * 16 + (lane >> 2), cb = (lane & 3) * 2;
#pragma unroll
    for (int j = 0; j < 8; j++) {
        int col = h * 64 + 8 * j + cb;
        {
            int tok = t0 + qb * 64 + r0;
            uint32_t ph, pl;
            psplit2(o[j][0] * inv0, o[j][1] * inv0, ph, pl);
            *(uint32_t*)&g_ath[(size_t)tok * DIMSZ + col] = ph;
            *(uint32_t*)&g_atl[(size_t)tok * DIMSZ + col] = pl;
        }
        {
            int tok = t0 + qb * 64 + r0 + 8;
            uint32_t ph, pl;
            psplit2(o[j][2] * inv1, o[j][3] * inv1, ph, pl);
            *(uint32_t*)&g_ath[(size_t)tok * DIMSZ + col] = ph;
            *(uint32_t*)&g_atl[(size_t)tok * DIMSZ + col] = pl;
        }
    }
#undef A_ISSUE
}

// ---------------------------------------------------------------------------
extern "C" void kernel_launch(void* const* d_in, const int* in_sizes, int n_in,
                              void* d_out, int out_size) {
    const float* x     = (const float*)d_in[0];
    const float* gamma = (const float*)d_in[1];
    const float* w_qkv = (const float*)d_in[2];
    const float* w_out = (const float*)d_in[3];
    float*       out   = (float*)d_out;
    (void)in_sizes; (void)n_in; (void)out_size;

    bf16 *p_xnh, *p_xnl, *p_wqh, *p_wql, *p_qvh, *p_qvl, *p_ath, *p_atl, *p_woh, *p_wol;
    cudaGetSymbolAddress((void**)&p_xnh, g_xnh);
    cudaGetSymbolAddress((void**)&p_xnl, g_xnl);
    cudaGetSymbolAddress((void**)&p_wqh, g_wqh);
    cudaGetSymbolAddress((void**)&p_wql, g_wql);
    cudaGetSymbolAddress((void**)&p_qvh, g_qkvh);
    cudaGetSymbolAddress((void**)&p_qvl, g_qkvl);
    cudaGetSymbolAddress((void**)&p_ath, g_ath);
    cudaGetSymbolAddress((void**)&p_atl, g_atl);
    cudaGetSymbolAddress((void**)&p_woh, g_woh);
    cudaGetSymbolAddress((void**)&p_wol, g_wol);

    static int attr_set = 0;
    if (!attr_set) {
        cudaFuncSetAttribute(gemm_mma<1>, cudaFuncAttributeMaxDynamicSharedMemorySize, GEMM_SMEM);
        cudaFuncSetAttribute(gemm_mma<0>, cudaFuncAttributeMaxDynamicSharedMemorySize, GEMM_SMEM);
        cudaFuncSetAttribute(attn_mma,    cudaFuncAttributeMaxDynamicSharedMemorySize, ATTN_SMEM);
        attr_set = 1;
    }

    rmsnorm_kernel<<<TOKENS, 256>>>(x, gamma);
    tsplit_kernel<<<dim3(QKV_N / 32, DIMSZ / 32), dim3(32, 8)>>>(w_qkv, p_wqh, p_wql, DIMSZ, QKV_N);
    tsplit_kernel<<<dim3(DIMSZ / 32, DIMSZ / 32), dim3(32, 8)>>>(w_out, p_woh, p_wol, DIMSZ, DIMSZ);
    gemm_mma<1><<<dim3(QKV_N / 128, TOKENS / 128), 256, GEMM_SMEM>>>(
        p_xnh, p_xnl, p_wqh, p_wql, nullptr, p_qvh, p_qvl, QKV_N);
    attn_mma<<<dim3(NSEQ / 64, 2 * HEADS), 128, ATTN_SMEM>>>();
    gemm_mma<0><<<dim3(DIMSZ / 128, TOKENS / 128), 256, GEMM_SMEM>>>(
        p_ath, p_atl, p_woh, p_wol, out, nullptr, nullptr, DIMSZ);
}

// round 15
// speedup vs baseline: 1.1091x; 1.1091x over previous
#include <cuda_runtime.h>
#include <cuda_bf16.h>
#include <cstdint>

#define TOKENS 4096
#define DIMSZ  1024
#define NSEQ   2048
#define HEADS  16
#define QKV_N  3072

typedef __nv_bfloat16 bf16;

// Scratch (device globals per harness rules; 16B-aligned for cp.async/uint4)
__device__ __align__(16) bf16 g_xnh [TOKENS * DIMSZ];
__device__ __align__(16) bf16 g_xnl [TOKENS * DIMSZ];
__device__ __align__(16) bf16 g_wqh [QKV_N * DIMSZ];
__device__ __align__(16) bf16 g_wql [QKV_N * DIMSZ];
__device__ __align__(16) bf16 g_qkvh[TOKENS * QKV_N];   // split QKV (Q pre-scaled)
__device__ __align__(16) bf16 g_qkvl[TOKENS * QKV_N];
__device__ __align__(16) bf16 g_ath [TOKENS * DIMSZ];
__device__ __align__(16) bf16 g_atl [TOKENS * DIMSZ];
__device__ __align__(16) bf16 g_woh [DIMSZ * DIMSZ];
__device__ __align__(16) bf16 g_wol [DIMSZ * DIMSZ];

__device__ __forceinline__ uint32_t smem_u32(const void* p) {
    uint32_t a;
    asm("{ .reg .u64 t; cvta.to.shared.u64 t, %1; cvt.u32.u64 %0, t; }" : "=r"(a) : "l"(p));
    return a;
}
__device__ __forceinline__ void split(float v, bf16& h, bf16& l) {
    h = __float2bfloat16(v);
    l = __float2bfloat16(v - __bfloat162float(h));
}
__device__ __forceinline__ void ldsm_x4(uint32_t* r, uint32_t addr) {
    asm volatile("ldmatrix.sync.aligned.m8n8.x4.shared.b16 {%0,%1,%2,%3}, [%4];"
        : "=r"(r[0]), "=r"(r[1]), "=r"(r[2]), "=r"(r[3]) : "r"(addr));
}
__device__ __forceinline__ void ldsm_x4_t(uint32_t* r, uint32_t addr) {
    asm volatile("ldmatrix.sync.aligned.m8n8.x4.trans.shared.b16 {%0,%1,%2,%3}, [%4];"
        : "=r"(r[0]), "=r"(r[1]), "=r"(r[2]), "=r"(r[3]) : "r"(addr));
}
__device__ __forceinline__ void mma_bf16(float* c, const uint32_t* a, uint32_t b0, uint32_t b1) {
    asm volatile(
        "mma.sync.aligned.m16n8k16.row.col.f32.bf16.bf16.f32 "
        "{%0,%1,%2,%3}, {%4,%5,%6,%7}, {%8,%9}, {%0,%1,%2,%3};"
        : "+f"(c[0]), "+f"(c[1]), "+f"(c[2]), "+f"(c[3])
        : "r"(a[0]), "r"(a[1]), "r"(a[2]), "r"(a[3]), "r"(b0), "r"(b1));
}
__device__ __forceinline__ void psplit2(float x, float y, uint32_t& ph, uint32_t& pl) {
    bf16 hx = __float2bfloat16(x), hy = __float2bfloat16(y);
    bf16 lx = __float2bfloat16(x - __bfloat162float(hx));
    bf16 ly = __float2bfloat16(y - __bfloat162float(hy));
    ph = ((uint32_t)__bfloat16_as_ushort(hy) << 16) | __bfloat16_as_ushort(hx);
    pl = ((uint32_t)__bfloat16_as_ushort(ly) << 16) | __bfloat16_as_ushort(lx);
}

#define CP16(dst, src)  asm volatile("cp.async.cg.shared.global [%0], [%1], 16;" :: "r"(dst), "l"(src))
#define CP_COMMIT()     asm volatile("cp.async.commit_group;" ::: "memory")
#define CP_WAIT(n)      asm volatile("cp.async.wait_group %0;" :: "n"(n) : "memory")

// ---------------------------------------------------------------------------
// RMSNorm -> split bf16 hi/lo
// ---------------------------------------------------------------------------
__global__ void __launch_bounds__(256) rmsnorm_kernel(const float* __restrict__ x,
                                                      const float* __restrict__ gamma) {
    int row = blockIdx.x;
    int tid = threadIdx.x;
    const float4 v = ((const float4*)(x + (size_t)row * DIMSZ))[tid];
    float ss = v.x * v.x + v.y * v.y + v.z * v.z + v.w * v.w;
#pragma unroll
    for (int off = 16; off >= 1; off >>= 1)
        ss += __shfl_xor_sync(0xffffffffu, ss, off);
    __shared__ float red[8];
    int lane = tid & 31, wid = tid >> 5;
    if (lane == 0) red[wid] = ss;
    __syncthreads();
    if (wid == 0) {
        float t = (lane < 8) ? red[lane] : 0.0f;
#pragma unroll
        for (int off = 4; off >= 1; off >>= 1)
            t += __shfl_xor_sync(0xffffffffu, t, off);
        if (lane == 0) red[0] = t;
    }
    __syncthreads();
    float norm = fmaxf(sqrtf(red[0]), 1e-12f);
    float scl = 32.0f / norm;
    const float4 g = ((const float4*)gamma)[tid];
    float o0 = v.x * scl * g.x, o1 = v.y * scl * g.y;
    float o2 = v.z * scl * g.z, o3 = v.w * scl * g.w;
    __align__(8) bf16 hh[4], ll[4];
    split(o0, hh[0], ll[0]); split(o1, hh[1], ll[1]);
    split(o2, hh[2], ll[2]); split(o3, hh[3], ll[3]);
    size_t off = (size_t)row * DIMSZ + tid * 4;
    *(uint2*)&g_xnh[off] = *(uint2*)hh;
    *(uint2*)&g_xnl[off] = *(uint2*)ll;
}

// ---------------------------------------------------------------------------
// Transpose + split: W[K][N] fp32 -> Th/Tl[N][K] bf16
// ---------------------------------------------------------------------------
__global__ void tsplit_kernel(const float* __restrict__ W, bf16* __restrict__ Th,
                              bf16* __restrict__ Tl, int K, int N) {
    __shared__ float s[32][33];
    int tx = threadIdx.x, ty = threadIdx.y;
    int n0 = blockIdx.x * 32, k0 = blockIdx.y * 32;
#pragma unroll
    for (int j = 0; j < 32; j += 8)
        s[ty + j][tx] = W[(size_t)(k0 + ty + j) * N + n0 + tx];
    __syncthreads();
#pragma unroll
    for (int j = 0; j < 32; j += 8) {
        float v = s[tx][ty + j];
        bf16 h, l; split(v, h, l);
        size_t o = (size_t)(n0 + ty + j) * K + k0 + tx;
        Th[o] = h; Tl[o] = l;
    }
}

// ---------------------------------------------------------------------------
// Split-bf16 mma.sync GEMM, cp.async 3-stage pipeline, K-slab 32.
// C[M,N] = A[M,1024] @ Bt[N,1024]^T ~= Ah·Bh + Ah·Bl + Al·Bh
// Smem: 64B row pitch, XOR swizzle (chunk ^= (row>>1)&3) -> conflict-free
// ldmatrix with zero padding. Stage = 32KB, 3 stages = 96KB -> 2 CTAs/SM.
// One __syncthreads per slab (issue-distance 2).
// ---------------------------------------------------------------------------
#define G_AB   8192u               // per array: 128 rows x 64B
#define G_STG  (4u * G_AB)         // 32768 B per stage
#define GEMM_SMEM (3 * G_STG)      // 98304 B

template<int SPLIT>
__global__ void __launch_bounds__(256, 2) gemm_mma(
        const bf16* __restrict__ Ah, const bf16* __restrict__ Al,
        const bf16* __restrict__ Bh, const bf16* __restrict__ Bl,
        float* __restrict__ C, bf16* __restrict__ Ch, bf16* __restrict__ Cl, int N) {
    extern __shared__ char smraw[];
    uint32_t sbase = smem_u32(smraw);
    int tid = threadIdx.x, lane = tid & 31, wid = tid >> 5;
    int wm = wid >> 2, wn = wid & 3;
    int bm = blockIdx.y * 128, bn = blockIdx.x * 128;

    const bf16* g0 = Ah + (size_t)bm * DIMSZ;
    const bf16* g1 = Al + (size_t)bm * DIMSZ;
    const bf16* g2 = Bh + (size_t)bn * DIMSZ;
    const bf16* g3 = Bl + (size_t)bn * DIMSZ;

    // ldmatrix lane bases (row part); swizzle nibble invariant under +16-row steps
    int arow = wm * 64 + (lane & 7) + ((lane >> 3) & 1) * 8;
    uint32_t ahi = (uint32_t)(lane >> 4);           // k-chunk bit for A
    uint32_t asw = (uint32_t)((arow >> 1) & 3);
    int nrow = wn * 32 + (lane & 7) + ((lane >> 4) & 1) * 8;
    uint32_t bhi = (uint32_t)((lane >> 3) & 1);     // k-chunk bit for B
    uint32_t bsw = (uint32_t)((nrow >> 1) & 3);

    float c[4][4][4];
#pragma unroll
    for (int i = 0; i < 4; i++)
#pragma unroll
        for (int j = 0; j < 4; j++)
#pragma unroll
            for (int k = 0; k < 4; k++) c[i][j][k] = 0.0f;

    // copy coords: 512 chunks/array/slab, 2 per thread per array
#define G_ISSUE(s, stg) do {                                                      \
    int k0_ = (s) * 32;                                                           \
    uint32_t db_ = sbase + (stg) * G_STG;                                         \
    _Pragma("unroll")                                                             \
    for (int t = 0; t < 2; t++) {                                                 \
        int idx = tid + t * 256;                                                  \
        int row = idx >> 2, cc = idx & 3;                                         \
        uint32_t doff = (uint32_t)(row * 64) + ((cc ^ ((row >> 1) & 3)) << 4);    \
        CP16(db_ + 0 * G_AB + doff, g0 + (size_t)row * DIMSZ + k0_ + cc * 8);     \
        CP16(db_ + 1 * G_AB + doff, g1 + (size_t)row * DIMSZ + k0_ + cc * 8);     \
        CP16(db_ + 2 * G_AB + doff, g2 + (size_t)row * DIMSZ + k0_ + cc * 8);     \
        CP16(db_ + 3 * G_AB + doff, g3 + (size_t)row * DIMSZ + k0_ + cc * 8);     \
    }                                                                             \
    CP_COMMIT();                                                                  \
} while (0)

    G_ISSUE(0, 0);
    G_ISSUE(1, 1);

    const int NSLAB = DIMSZ / 32;  // 32
    int stg = 0;
    for (int s = 0; s < NSLAB; s++) {
        if (s < NSLAB - 1) CP_WAIT(1);
        else               CP_WAIT(0);
        __syncthreads();                     // slab s visible to all; stage (s+2)%3 free
        if (s + 2 < NSLAB) {
            int ns = stg + 2; if (ns >= 3) ns -= 3;
            G_ISSUE(s + 2, ns);
        }
        uint32_t sb = sbase + stg * G_STG;
#pragma unroll
        for (int kk = 0; kk < 2; kk++) {
            uint32_t ach = ((kk * 2 + ahi) ^ asw) << 4;
            uint32_t bch = ((kk * 2 + bhi) ^ bsw) << 4;
            uint32_t aH[4][4], aL[4][4], bH[2][4], bL[2][4];
#pragma unroll
            for (int mt = 0; mt < 4; mt++) {
                uint32_t ro = (uint32_t)((arow + mt * 16) * 64) + ach;
                ldsm_x4(aH[mt], sb + 0 * G_AB + ro);
                ldsm_x4(aL[mt], sb + 1 * G_AB + ro);
            }
#pragma unroll
            for (int pr = 0; pr < 2; pr++) {
                uint32_t ro = (uint32_t)((nrow + pr * 16) * 64) + bch;
                ldsm_x4(bH[pr], sb + 2 * G_AB + ro);
                ldsm_x4(bL[pr], sb + 3 * G_AB + ro);
            }
#pragma unroll
            for (int mt = 0; mt < 4; mt++)
#pragma unroll
                for (int nt = 0; nt < 4; nt++) {
                    int pr = nt >> 1, hf = (nt & 1) * 2;
                    mma_bf16(c[mt][nt], aH[mt], bH[pr][hf], bH[pr][hf + 1]);
                    mma_bf16(c[mt][nt], aH[mt], bL[pr][hf], bL[pr][hf + 1]);
                    mma_bf16(c[mt][nt], aL[mt], bH[pr][hf], bH[pr][hf + 1]);
                }
        }
        stg = (stg + 1 == 3) ? 0 : stg + 1;
    }

    float sc = (SPLIT && bn < 1024) ? 0.125f : 1.0f;
#pragma unroll
    for (int mt = 0; mt < 4; mt++)
#pragma unroll
        for (int nt = 0; nt < 4; nt++) {
            int r0 = bm + wm * 64 + mt * 16 + (lane >> 2);
            int col = bn + wn * 32 + nt * 8 + (lane & 3) * 2;
            if (SPLIT) {
#pragma unroll
                for (int hrow = 0; hrow < 2; hrow++) {
                    float v0 = c[mt][nt][2 * hrow] * sc, v1 = c[mt][nt][2 * hrow + 1] * sc;
                    uint32_t ph, pl;
                    psplit2(v0, v1, ph, pl);
                    size_t o = (size_t)(r0 + 8 * hrow) * N + col;
                    *(uint32_t*)&Ch[o] = ph;
                    *(uint32_t*)&Cl[o] = pl;
                }
            } else {
                *(float2*)&C[(size_t)r0 * N + col]       = make_float2(c[mt][nt][0], c[mt][nt][1]);
                *(float2*)&C[(size_t)(r0 + 8) * N + col] = make_float2(c[mt][nt][2], c[mt][nt][3]);
            }
        }
#undef G_ISSUE
}

// ---------------------------------------------------------------------------
// Causal flash attention, split-bf16 mma.sync, cp.async double-buffered K/V.
// (R11 structure; q-blocks processed heaviest-first for tail balance.)
// ---------------------------------------------------------------------------
#define AP    72
#define A_AB  (64 * AP * 2)        // 9216 B per array
#define A_STG (4 * A_AB)           // 36864 B per stage
#define ATTN_SMEM (2 * A_STG)      // 73728 B

__global__ void __launch_bounds__(128) attn_mma() {
    extern __shared__ char smraw[];
    uint32_t sbase = smem_u32(smraw);
    int tid = threadIdx.x, lane = tid & 31, w = tid >> 5;
    int qb = (NSEQ / 64 - 1) - blockIdx.x;      // heavy CTAs first
    int bh = blockIdx.y;
    int b = bh >> 4, h = bh & 15;
    int t0 = b * NSEQ;

#define A_ISSUE(kb, stg) do {                                                        \
    uint32_t db_ = sbase + (stg) * A_STG;                                            \
    _Pragma("unroll")                                                                \
    for (int t = 0; t < 4; t++) {                                                    \
        int idx = tid + t * 128;                                                     \
        int row = idx >> 3, ch = (idx & 7) * 8;                                      \
        uint32_t doff = (uint32_t)(row * AP + ch) * 2;                               \
        size_t g = (size_t)(t0 + (kb) * 64 + row) * QKV_N + h * 64 + ch;             \
        CP16(db_ + 0 * A_AB + doff, &g_qkvh[g + 1024]);                              \
        CP16(db_ + 1 * A_AB + doff, &g_qkvl[g + 1024]);                              \
        CP16(db_ + 2 * A_AB + doff, &g_qkvh[g + 2048]);                              \
        CP16(db_ + 3 * A_AB + doff, &g_qkvl[g + 2048]);                              \
    }                                                                                \
    CP_COMMIT();                                                                     \
} while (0)

    A_ISSUE(0, 0);   // K/V block 0 -> stage 0 (async, overlaps Q staging)

    // stage Q (bf16, pre-scaled) into stage-1 Kh/Kl regions
#pragma unroll
    for (int t = 0; t < 4; t++) {
        int idx = tid + t * 128;
        int row = idx >> 3, ch = (idx & 7) * 8;
        size_t g = (size_t)(t0 + qb * 64 + row) * QKV_N + h * 64 + ch;
        uint32_t doff = (uint32_t)(row * AP + ch) * 2;
        *(uint4*)(smraw + A_STG + 0 * A_AB + doff) = *(const uint4*)&g_qkvh[g];
        *(uint4*)(smraw + A_STG + 1 * A_AB + doff) = *(const uint4*)&g_qkvl[g];
    }
    __syncthreads();
    uint32_t qh[4][4], ql[4][4];
    {
        int rowA = w * 16 + (lane & 7) + ((lane >> 3) & 1) * 8;
        int koffA = (lane >> 4) * 8;
        uint32_t aHb = sbase + A_STG + 0 * A_AB + (uint32_t)(rowA * AP + koffA) * 2;
        uint32_t aLb = sbase + A_STG + 1 * A_AB + (uint32_t)(rowA * AP + koffA) * 2;
#pragma unroll
        for (int k = 0; k < 4; k++) {
            ldsm_x4(qh[k], aHb + k * 32);
            ldsm_x4(ql[k], aLb + k * 32);
        }
    }
    __syncthreads();   // all warps have Q frags before stage-1 gets overwritten

    float o[8][4];
#pragma unroll
    for (int j = 0; j < 8; j++)
#pragma unroll
        for (int v = 0; v < 4; v++) o[j][v] = 0.0f;
    float m0 = -1e30f, m1 = -1e30f, l0 = 0.0f, l1 = 0.0f;

    int nrowB = (lane & 7) + ((lane >> 4) & 1) * 8;
    int koffB = ((lane >> 3) & 1) * 8;
    uint32_t kboff = (uint32_t)(nrowB * AP + koffB) * 2;
    uint32_t vboff = (uint32_t)((lane & 15) * AP + ((lane >> 4) & 1) * 8) * 2;

    for (int kb = 0; kb <= qb; kb++) {
        int stg = kb & 1;
        if (kb < qb) { A_ISSUE(kb + 1, stg ^ 1); CP_WAIT(1); }
        else         { CP_WAIT(0); }
        __syncthreads();
        uint32_t sb = sbase + stg * A_STG;
        uint32_t kHb = sb + kboff, kLb = sb + A_AB + kboff;
        uint32_t vHb = sb + 2 * A_AB + vboff, vLb = sb + 3 * A_AB + vboff;

        // ---- S = Q K^T ----
        float s[8][4];
#pragma unroll
        for (int j = 0; j < 8; j++)
#pragma unroll
            for (int v = 0; v < 4; v++) s[j][v] = 0.0f;
#pragma unroll
        for (int k = 0; k < 4; k++)
#pragma unroll
            for (int pr = 0; pr < 4; pr++) {
                uint32_t bh_[4], bl_[4];
                ldsm_x4(bh_, kHb + pr * (16 * AP * 2) + k * 32);
                ldsm_x4(bl_, kLb + pr * (16 * AP * 2) + k * 32);
                mma_bf16(s[2 * pr],     qh[k], bh_[0], bh_[1]);
                mma_bf16(s[2 * pr],     qh[k], bl_[0], bl_[1]);
                mma_bf16(s[2 * pr],     ql[k], bh_[0], bh_[1]);
                mma_bf16(s[2 * pr + 1], qh[k], bh_[2], bh_[3]);
                mma_bf16(s[2 * pr + 1], qh[k], bl_[2], bl_[3]);
                mma_bf16(s[2 * pr + 1], ql[k], bh_[2], bh_[3]);
            }

        int r0 = w * 16 + (lane >> 2);
        int cb = (lane & 3) * 2;
        if (kb == qb) {
#pragma unroll
            for (int j = 0; j < 8; j++) {
                int c0 = 8 * j + cb;
                if (c0     > r0    ) s[j][0] = -1e30f;
                if (c0 + 1 > r0    ) s[j][1] = -1e30f;
                if (c0     > r0 + 8) s[j][2] = -1e30f;
                if (c0 + 1 > r0 + 8) s[j][3] = -1e30f;
            }
        }

        // ---- online softmax (2 rows/thread) ----
        float tm0 = -1e30f, tm1 = -1e30f;
#pragma unroll
        for (int j = 0; j < 8; j++) {
            tm0 = fmaxf(tm0, fmaxf(s[j][0], s[j][1]));
            tm1 = fmaxf(tm1, fmaxf(s[j][2], s[j][3]));
        }
        tm0 = fmaxf(tm0, __shfl_xor_sync(0xffffffffu, tm0, 1));
        tm0 = fmaxf(tm0, __shfl_xor_sync(0xffffffffu, tm0, 2));
        tm1 = fmaxf(tm1, __shfl_xor_sync(0xffffffffu, tm1, 1));
        tm1 = fmaxf(tm1, __shfl_xor_sync(0xffffffffu, tm1, 2));
        float mn0 = fmaxf(m0, tm0), mn1 = fmaxf(m1, tm1);
        float al0 = __expf(m0 - mn0), al1 = __expf(m1 - mn1);
        m0 = mn0; m1 = mn1;
        float sum0 = 0.0f, sum1 = 0.0f;
#pragma unroll
        for (int j = 0; j < 8; j++) {
            s[j][0] = __expf(s[j][0] - mn0); sum0 += s[j][0];
            s[j][1] = __expf(s[j][1] - mn0); sum0 += s[j][1];
            s[j][2] = __expf(s[j][2] - mn1); sum1 += s[j][2];
            s[j][3] = __expf(s[j][3] - mn1); sum1 += s[j][3];
        }
        sum0 += __shfl_xor_sync(0xffffffffu, sum0, 1);
        sum0 += __shfl_xor_sync(0xffffffffu, sum0, 2);
        sum1 += __shfl_xor_sync(0xffffffffu, sum1, 1);
        sum1 += __shfl_xor_sync(0xffffffffu, sum1, 2);
        l0 = l0 * al0 + sum0;
        l1 = l1 * al1 + sum1;
#pragma unroll
        for (int j = 0; j < 8; j++) {
            o[j][0] *= al0; o[j][1] *= al0;
            o[j][2] *= al1; o[j][3] *= al1;
        }

        // ---- O += P V ----
#pragma unroll
        for (int kk = 0; kk < 4; kk++) {
            uint32_t ph[4], pl[4];
            psplit2(s[2 * kk][0],     s[2 * kk][1],     ph[0], pl[0]);
            psplit2(s[2 * kk][2],     s[2 * kk][3],     ph[1], pl[1]);
            psplit2(s[2 * kk + 1][0], s[2 * kk + 1][1], ph[2], pl[2]);
            psplit2(s[2 * kk + 1][2], s[2 * kk + 1][3], ph[3], pl[3]);
#pragma unroll
            for (int pr = 0; pr < 4; pr++) {
                uint32_t bvh[4], bvl[4];
                ldsm_x4_t(bvh, vHb + (uint32_t)(kk * 16 * AP + pr * 16) * 2);
                ldsm_x4_t(bvl, vLb + (uint32_t)(kk * 16 * AP + pr * 16) * 2);
                mma_bf16(o[2 * pr],     ph, bvh[0], bvh[1]);
                mma_bf16(o[2 * pr],     pl, bvh[0], bvh[1]);
                mma_bf16(o[2 * pr],     ph, bvl[0], bvl[1]);
                mma_bf16(o[2 * pr + 1], ph, bvh[2], bvh[3]);
                mma_bf16(o[2 * pr + 1], pl, bvh[2], bvh[3]);
                mma_bf16(o[2 * pr + 1], ph, bvl[2], bvl[3]);
            }
        }
        __syncthreads();   // all warps done with this stage before it is refilled
    }

    // ---- epilogue ----
    float inv0 = 1.0f / l0, inv1 = 1.0f / l1;
    int r0 = w * 16 + (lane >> 2), cb = (lane & 3) * 2;
#pragma unroll
    for (int j = 0; j < 8; j++) {
        int col = h * 64 + 8 * j + cb;
        {
            int tok = t0 + qb * 64 + r0;
            uint32_t ph, pl;
            psplit2(o[j][0] * inv0, o[j][1] * inv0, ph, pl);
            *(uint32_t*)&g_ath[(size_t)tok * DIMSZ + col] = ph;
            *(uint32_t*)&g_atl[(size_t)tok * DIMSZ + col] = pl;
        }
        {
            int tok = t0 + qb * 64 + r0 + 8;
            uint32_t ph, pl;
            psplit2(o[j][2] * inv1, o[j][3] * inv1, ph, pl);
            *(uint32_t*)&g_ath[(size_t)tok * DIMSZ + col] = ph;
            *(uint32_t*)&g_atl[(size_t)tok * DIMSZ + col] = pl;
        }
    }
#undef A_ISSUE
}

// ---------------------------------------------------------------------------
extern "C" void kernel_launch(void* const* d_in, const int* in_sizes, int n_in,
                              void* d_out, int out_size) {
    const float* x     = (const float*)d_in[0];
    const float* gamma = (const float*)d_in[1];
    const float* w_qkv = (const float*)d_in[2];
    const float* w_out = (const float*)d_in[3];
    float*       out   = (float*)d_out;
    (void)in_sizes; (void)n_in; (void)out_size;

    bf16 *p_xnh, *p_xnl, *p_wqh, *p_wql, *p_qvh, *p_qvl, *p_ath, *p_atl, *p_woh, *p_wol;
    cudaGetSymbolAddress((void**)&p_xnh, g_xnh);
    cudaGetSymbolAddress((void**)&p_xnl, g_xnl);
    cudaGetSymbolAddress((void**)&p_wqh, g_wqh);
    cudaGetSymbolAddress((void**)&p_wql, g_wql);
    cudaGetSymbolAddress((void**)&p_qvh, g_qkvh);
    cudaGetSymbolAddress((void**)&p_qvl, g_qkvl);
    cudaGetSymbolAddress((void**)&p_ath, g_ath);
    cudaGetSymbolAddress((void**)&p_atl, g_atl);
    cudaGetSymbolAddress((void**)&p_woh, g_woh);
    cudaGetSymbolAddress((void**)&p_wol, g_wol);

    static int attr_set = 0;
    if (!attr_set) {
        cudaFuncSetAttribute(gemm_mma<1>, cudaFuncAttributeMaxDynamicSharedMemorySize, GEMM_SMEM);
        cudaFuncSetAttribute(gemm_mma<0>, cudaFuncAttributeMaxDynamicSharedMemorySize, GEMM_SMEM);
        cudaFuncSetAttribute(attn_mma,    cudaFuncAttributeMaxDynamicSharedMemorySize, ATTN_SMEM);
        attr_set = 1;
    }

    rmsnorm_kernel<<<TOKENS, 256>>>(x, gamma);
    tsplit_kernel<<<dim3(QKV_N / 32, DIMSZ / 32), dim3(32, 8)>>>(w_qkv, p_wqh, p_wql, DIMSZ, QKV_N);
    tsplit_kernel<<<dim3(DIMSZ / 32, DIMSZ / 32), dim3(32, 8)>>>(w_out, p_woh, p_wol, DIMSZ, DIMSZ);
    gemm_mma<1><<<dim3(QKV_N / 128, TOKENS / 128), 256, GEMM_SMEM>>>(
        p_xnh, p_xnl, p_wqh, p_wql, nullptr, p_qvh, p_qvl, QKV_N);
    attn_mma<<<dim3(NSEQ / 64, 2 * HEADS), 128, ATTN_SMEM>>>();
    gemm_mma<0><<<dim3(DIMSZ / 128, TOKENS / 128), 256, GEMM_SMEM>>>(
        p_ath, p_atl, p_woh, p_wol, out, nullptr, nullptr, DIMSZ);
}